// round 4
// baseline (speedup 1.0000x reference)
#include <cuda_runtime.h>

#define NN   100000
#define DD   128
#define EE   600000
#define SS   2
#define HIDN 80
#define NOUT 2

// Scratch (allocation-free: __device__ globals)
__device__ __align__(16) unsigned char g_mask[SS * NN];  // dst-indicator per edge set
__device__ float g_sum[SS * DD];                         // masked column sums
__device__ float g_x[DD];                                // gemv result (pre /N)
__device__ float g_sink;                                 // never-written warm sink

// ---------------------------------------------------------------------------
// K1: zero masks + accumulators, AND warm L2 with W/fc weights so the
// latency-bound epilogue kernels hit L2 instead of cold DRAM.
// ---------------------------------------------------------------------------
__global__ void k_zero(const float* __restrict__ W,
                       const float* __restrict__ fc1w,
                       const float* __restrict__ fc2w,
                       const float* __restrict__ fc3w) {
    int idx = blockIdx.x * blockDim.x + threadIdx.x;
    int stride = gridDim.x * blockDim.x;
    uint4* m = reinterpret_cast<uint4*>(g_mask);
    const int total16 = (SS * NN) / 16;  // 12500
    for (int i = idx; i < total16; i += stride)
        m[i] = make_uint4(0u, 0u, 0u, 0u);
    if (idx < SS * DD) g_sum[idx] = 0.0f;
    if (idx < DD) g_x[idx] = 0.0f;

    // L2 warm: data-dependent accumulate, store guarded by improbable value.
    float acc = 0.0f;
    for (int i = idx; i < SS * DD * DD; i += stride) acc += W[i];
    for (int i = idx; i < HIDN * (DD + 1); i += stride) acc += fc1w[i];
    for (int i = idx; i < HIDN * HIDN; i += stride) acc += fc2w[i];
    for (int i = idx; i < NOUT * HIDN; i += stride) acc += fc3w[i];
    if (acc == 1.2345678e+31f) g_sink = acc;  // effectively never
}

// ---------------------------------------------------------------------------
// K2: mark nodes that appear as dst in each edge set
// edges layout: (S, E, 2) int32 -> int2 per edge, .y = dst
// ---------------------------------------------------------------------------
__global__ void k_mask(const int2* __restrict__ edges) {
    int e = blockIdx.x * blockDim.x + threadIdx.x;
    const int total = SS * EE;
    if (e >= total) return;
    int2 v = edges[e];
    int s_off = (e >= EE) ? NN : 0;
    g_mask[s_off + v.y] = 1;
}

// ---------------------------------------------------------------------------
// K3: masked column sums of nodes (N x D), float4 + unroll 8 for deep MLP.
// Thread layout: q = tid&31 -> float4 column group, r = tid>>5 -> row-sub.
// Block processes 4 rows per step; smem reduce before atomics.
// ---------------------------------------------------------------------------
#define SUM_GRID 592
#define SUM_UNROLL 8

__global__ void k_sum(const float4* __restrict__ nodes4) {
    const int q = threadIdx.x & 31;   // float4 index within row (cols 4q..4q+3)
    const int r = threadIdx.x >> 5;   // 0..3
    const int G = SUM_GRID;

    float4 a0 = make_float4(0.f, 0.f, 0.f, 0.f);
    float4 a1 = make_float4(0.f, 0.f, 0.f, 0.f);

    for (int n0 = blockIdx.x * 4 + r; n0 < NN; n0 += 4 * G * SUM_UNROLL) {
#pragma unroll
        for (int u = 0; u < SUM_UNROLL; u++) {
            int nn = n0 + u * 4 * G;
            if (nn < NN) {
                float4 v = nodes4[(size_t)nn * 32 + q];
                float m0 = (float)g_mask[nn];
                float m1 = (float)g_mask[NN + nn];
                a0.x += v.x * m0; a0.y += v.y * m0; a0.z += v.z * m0; a0.w += v.w * m0;
                a1.x += v.x * m1; a1.y += v.y * m1; a1.z += v.z * m1; a1.w += v.w * m1;
            }
        }
    }

    __shared__ float4 s0[4][32], s1[4][32];
    s0[r][q] = a0; s1[r][q] = a1;
    __syncthreads();
    if (r == 0) {
#pragma unroll
        for (int i = 1; i < 4; i++) {
            float4 b0 = s0[i][q], b1 = s1[i][q];
            a0.x += b0.x; a0.y += b0.y; a0.z += b0.z; a0.w += b0.w;
            a1.x += b1.x; a1.y += b1.y; a1.z += b1.z; a1.w += b1.w;
        }
        atomicAdd(&g_sum[4 * q + 0], a0.x);
        atomicAdd(&g_sum[4 * q + 1], a0.y);
        atomicAdd(&g_sum[4 * q + 2], a0.z);
        atomicAdd(&g_sum[4 * q + 3], a0.w);
        atomicAdd(&g_sum[DD + 4 * q + 0], a1.x);
        atomicAdd(&g_sum[DD + 4 * q + 1], a1.y);
        atomicAdd(&g_sum[DD + 4 * q + 2], a1.z);
        atomicAdd(&g_sum[DD + 4 * q + 3], a1.w);
    }
}

// ---------------------------------------------------------------------------
// K4: wide GEMV  x_d = sum_k s0[k]*W0[k][d] + s1[k]*W1[k][d]
// 128 blocks, block b handles k=b for BOTH edge sets (2 coalesced W rows).
// W is L2-warm from k_zero -> ~250cyc loads.
// ---------------------------------------------------------------------------
__global__ void k_gemv(const float* __restrict__ W) {
    const int t = threadIdx.x;   // output column d
    const int k = blockIdx.x;    // 0..127
    float s0 = g_sum[k];
    float s1 = g_sum[DD + k];
    float acc = s0 * W[k * DD + t] + s1 * W[DD * DD + k * DD + t];
    atomicAdd(&g_x[t], acc);
}

// ---------------------------------------------------------------------------
// K5: MLP 129 -> 80 -> 80 -> 2, one block of 1024 threads, warp-per-row.
// ---------------------------------------------------------------------------
__device__ __forceinline__ float lrelu(float x) {
    return x > 0.0f ? x : 0.01f * x;
}

__device__ __forceinline__ float warp_reduce(float v) {
#pragma unroll
    for (int off = 16; off > 0; off >>= 1)
        v += __shfl_down_sync(0xFFFFFFFFu, v, off);
    return v;
}

__global__ void k_mlp(const float* __restrict__ pt,
                      const float* __restrict__ fc1w, const float* __restrict__ fc1b,
                      const float* __restrict__ fc2w, const float* __restrict__ fc2b,
                      const float* __restrict__ fc3w, const float* __restrict__ fc3b,
                      float* __restrict__ out) {
    __shared__ float x[DD + 1], h1[HIDN], h2[HIDN];
    const int t    = threadIdx.x;     // 0..1023
    const int warp = t >> 5;          // 0..31
    const int lane = t & 31;

    if (t < DD) x[t] = g_x[t] * (1.0f / (float)NN);
    if (t == DD) x[DD] = pt[0];
    __syncthreads();

    // fc1: 80 rows x 129 cols, warp-per-row
    for (int row = warp; row < HIDN; row += 32) {
        float a = 0.0f;
#pragma unroll
        for (int j0 = 0; j0 < DD + 1; j0 += 32) {
            int j = j0 + lane;
            if (j < DD + 1) a += x[j] * fc1w[row * (DD + 1) + j];
        }
        a = warp_reduce(a);
        if (lane == 0) h1[row] = lrelu(a + fc1b[row]);
    }
    __syncthreads();

    // fc2: 80 rows x 80 cols
    for (int row = warp; row < HIDN; row += 32) {
        float a = 0.0f;
#pragma unroll
        for (int j0 = 0; j0 < HIDN; j0 += 32) {
            int j = j0 + lane;
            if (j < HIDN) a += h1[j] * fc2w[row * HIDN + j];
        }
        a = warp_reduce(a);
        if (lane == 0) h2[row] = lrelu(a + fc2b[row]);
    }
    __syncthreads();

    // fc3: 2 rows x 80 cols
    if (warp < NOUT) {
        float a = 0.0f;
#pragma unroll
        for (int j0 = 0; j0 < HIDN; j0 += 32) {
            int j = j0 + lane;
            if (j < HIDN) a += h2[j] * fc3w[warp * HIDN + j];
        }
        a = warp_reduce(a);
        if (lane == 0) out[warp] = a + fc3b[warp];
    }
}

// ---------------------------------------------------------------------------
// Input order (metadata): nodes, edges, problem_type, W, att_w, att_b,
//                         fc1_w, fc1_b, fc2_w, fc2_b, fc3_w, fc3_b
// ---------------------------------------------------------------------------
extern "C" void kernel_launch(void* const* d_in, const int* in_sizes, int n_in,
                              void* d_out, int out_size) {
    const float4* nodes4 = (const float4*)d_in[0];
    const int2*  edges = (const int2*)d_in[1];
    const float* pt    = (const float*)d_in[2];
    const float* W     = (const float*)d_in[3];
    // d_in[4] att_w, d_in[5] att_b: provably unused (softmax sums to 1)
    const float* fc1w  = (const float*)d_in[6];
    const float* fc1b  = (const float*)d_in[7];
    const float* fc2w  = (const float*)d_in[8];
    const float* fc2b  = (const float*)d_in[9];
    const float* fc3w  = (const float*)d_in[10];
    const float* fc3b  = (const float*)d_in[11];
    float* out = (float*)d_out;

    k_zero<<<64, 256>>>(W, fc1w, fc2w, fc3w);
    k_mask<<<(SS * EE + 255) / 256, 256>>>(edges);
    k_sum<<<SUM_GRID, 128>>>(nodes4);
    k_gemv<<<DD, DD>>>(W);
    k_mlp<<<1, 1024>>>(pt, fc1w, fc1b, fc2w, fc2b, fc3w, fc3b, out);
}